// round 13
// baseline (speedup 1.0000x reference)
#include <cuda_runtime.h>
#include <cuda_fp16.h>
#include <cstdint>
#include <cstddef>

// ===========================================================================
// INLAttentionBlock, fp16 tensor-core pipeline (mma.sync m16n8k16, f32 accum):
// prep(w->fp16 + GN stats) -> GN apply+T -> QKV -> flash -> 3x INL -> proj+res
// B=8, C=512, S=1024, nh=8, hd=64. Activations token-major [b, s, c].
// ===========================================================================

#define B_ 8
#define C_ 512
#define S_ 1024
#define NH 8
#define CS (C_ * S_)
#define CEXP 0.18033688011112042f   // 0.125 * log2(e)

__device__ __half g_hgn[(size_t)B_ * S_ * C_];        // [b, s, c] fp16
__device__ __half g_qkvT[(size_t)B_ * S_ * 1536];     // [b, s, 3C] fp16
__device__ float  g_h1f[(size_t)B_ * S_ * C_];        // fp32 shadow
__device__ __half g_h1h[(size_t)B_ * S_ * C_];
__device__ float  g_h2f[(size_t)B_ * S_ * C_];
__device__ __half g_h2h[(size_t)B_ * S_ * C_];
__device__ __half g_w16[1310720];                     // qkv|inl|proj fp16 weights
__device__ float  g_stats[2 * B_ * NH];
__device__ float2 g_part[512];

// ---------------------------------------------------------------------------
// helpers
// ---------------------------------------------------------------------------
__device__ __forceinline__ uint32_t smem_u32(const void* p) {
    uint32_t a;
    asm("{ .reg .u64 t; cvta.to.shared.u64 t, %1; cvt.u32.u64 %0, t; }" : "=r"(a) : "l"(p));
    return a;
}
__device__ __forceinline__ void ldsm4(uint32_t* r, uint32_t addr) {
    asm volatile("ldmatrix.sync.aligned.m8n8.x4.shared.b16 {%0,%1,%2,%3}, [%4];"
                 : "=r"(r[0]), "=r"(r[1]), "=r"(r[2]), "=r"(r[3]) : "r"(addr));
}
__device__ __forceinline__ void ldsm4t(uint32_t* r, uint32_t addr) {
    asm volatile("ldmatrix.sync.aligned.m8n8.x4.trans.shared.b16 {%0,%1,%2,%3}, [%4];"
                 : "=r"(r[0]), "=r"(r[1]), "=r"(r[2]), "=r"(r[3]) : "r"(addr));
}
__device__ __forceinline__ void mma16(float* d, const uint32_t* a, const uint32_t* b) {
    asm volatile("mma.sync.aligned.m16n8k16.row.col.f32.f16.f16.f32 "
                 "{%0,%1,%2,%3}, {%4,%5,%6,%7}, {%8,%9}, {%0,%1,%2,%3};"
                 : "+f"(d[0]), "+f"(d[1]), "+f"(d[2]), "+f"(d[3])
                 : "r"(a[0]), "r"(a[1]), "r"(a[2]), "r"(a[3]), "r"(b[0]), "r"(b[1]));
}
#define CP16(sa, ga) asm volatile("cp.async.cg.shared.global [%0], [%1], 16;" :: "r"(sa), "l"((const void*)(ga)))
#define CPCOMMIT()   asm volatile("cp.async.commit_group;" ::: "memory")
#define CPWAIT0()    asm volatile("cp.async.wait_group 0;" ::: "memory")

// ---------------------------------------------------------------------------
// prep: weights fp32->fp16 (blocks 0..639) + GN partial stats (blocks 640..1151)
// ---------------------------------------------------------------------------
__global__ void prep_kernel(const float* __restrict__ qkv_w,
                            const float* __restrict__ inl_w,
                            const float* __restrict__ proj_w,
                            __half* __restrict__ w16,
                            const float* __restrict__ x,
                            float2* __restrict__ part) {
    __shared__ float sh[256], sh2[256];
    const int bb = blockIdx.x;
    const int tid = threadIdx.x;
    if (bb < 640) {
        const float* s;
        __half* d = w16;
        int base;
        if (bb < 384)      { s = qkv_w;  base = bb * 2048; }
        else if (bb < 512) { s = inl_w;  base = (bb - 384) * 2048; d += 786432; }
        else               { s = proj_w; base = (bb - 512) * 2048; d += 1048576; }
        int i = base + tid * 8;
        float4 a = *(const float4*)(s + i);
        float4 b = *(const float4*)(s + i + 4);
        union { __half2 h[4]; uint4 u; } pk;
        pk.h[0] = __floats2half2_rn(a.x, a.y);
        pk.h[1] = __floats2half2_rn(a.z, a.w);
        pk.h[2] = __floats2half2_rn(b.x, b.y);
        pk.h[3] = __floats2half2_rn(b.z, b.w);
        *(uint4*)(d + i) = pk.u;
    } else {
        const int pb = bb - 640;
        const float4* p = (const float4*)(x + (size_t)pb * 8192);
        float s = 0.f, s2 = 0.f;
#pragma unroll
        for (int r = 0; r < 8; r++) {
            float4 v = p[tid + r * 256];
            s  += v.x + v.y + v.z + v.w;
            s2 += v.x * v.x + v.y * v.y + v.z * v.z + v.w * v.w;
        }
        sh[tid] = s; sh2[tid] = s2;
        __syncthreads();
        for (int st = 128; st > 0; st >>= 1) {
            if (tid < st) { sh[tid] += sh[tid + st]; sh2[tid] += sh2[tid + st]; }
            __syncthreads();
        }
        if (tid == 0) part[pb] = make_float2(sh[0], sh2[0]);
    }
}

__global__ void gn_stats_b_kernel(const float2* __restrict__ part, float* __restrict__ stats) {
    const int t = threadIdx.x;   // 512
    float2 p = part[t];
    float s = p.x, s2 = p.y;
#pragma unroll
    for (int o = 4; o > 0; o >>= 1) {
        s  += __shfl_down_sync(0xffffffffu, s,  o, 8);
        s2 += __shfl_down_sync(0xffffffffu, s2, o, 8);
    }
    if ((t & 7) == 0) {
        int g = t >> 3;
        float mean = s * (1.f / 65536.f);
        float var  = s2 * (1.f / 65536.f) - mean * mean;
        stats[2 * g]     = mean;
        stats[2 * g + 1] = rsqrtf(var + 1e-5f);
    }
}

// ---------------------------------------------------------------------------
// GN apply + transpose: 64c x 32s tiles, __half2 stores (full 128B rows)
// ---------------------------------------------------------------------------
__global__ void gn_apply_t_kernel(const float* __restrict__ x, const float* __restrict__ stats,
                                  const float* __restrict__ sc, const float* __restrict__ bi,
                                  __half* __restrict__ hgn) {
    __shared__ float t[64][33];
    const int b = blockIdx.z;
    const int c0 = blockIdx.y * 64;
    const int s0 = blockIdx.x * 32;
    const int tx = threadIdx.x, ty = threadIdx.y;
#pragma unroll
    for (int r = 0; r < 8; r++) {
        int cl = ty + r * 8;
        int c = c0 + cl;
        int bg = b * 8 + (c >> 6);
        float mean = stats[2 * bg], rstd = stats[2 * bg + 1];
        float a = rstd * sc[c];
        float bb = bi[c] - mean * a;
        t[cl][tx] = x[(size_t)b * CS + (size_t)c * S_ + s0 + tx] * a + bb;
    }
    __syncthreads();
#pragma unroll
    for (int r = 0; r < 4; r++) {
        int sl = ty + r * 8;
        int s = s0 + sl;
        __half2 v = __floats2half2_rn(t[tx * 2][sl], t[tx * 2 + 1][sl]);
        *(__half2*)(hgn + (size_t)b * CS + (size_t)s * C_ + c0 + tx * 2) = v;
    }
}

// ---------------------------------------------------------------------------
// Flash attention fp16: CTA = (b,h, 128 q rows). 256 thr / 8 warps.
// SMEM: [0,32K) warp P slices (Q staged in [0,16K) first),
//       [32K,64K) K0|V0, [64K,96K) K1|V1. K,V tiles: [t(128) x 64h] 128B rows.
// ---------------------------------------------------------------------------
__global__ void __launch_bounds__(256, 1) flash_kernel(
    const __half* __restrict__ qkvT, float* __restrict__ of, __half* __restrict__ oh)
{
    extern __shared__ char sm[];
    const uint32_t sb = smem_u32(sm);
    const int tid = threadIdx.x, wid = tid >> 5, lane = tid & 31;
    const int grp = lane >> 2, tig = lane & 3;
    const int b = blockIdx.z >> 3, h = blockIdx.z & 7;
    const int q0 = blockIdx.x * 128;
    const int wm0 = wid * 16;

    const __half* Qg = qkvT + (size_t)b * S_ * 1536 + (size_t)q0 * 1536 + h * 64;
    const __half* Kg = qkvT + (size_t)b * S_ * 1536 + 512 + h * 64;

    uint32_t so[4]; int go[4];
#pragma unroll
    for (int r = 0; r < 4; r++) {
        int li = tid + r * 256;
        int row = li >> 3, c8 = li & 7;
        so[r] = (uint32_t)(row * 128 + c8 * 16) ^ ((uint32_t)(row & 7) << 4);
        go[r] = row * 1536 + c8 * 8;
    }

    const uint32_t KV0 = sb + 32768;
#pragma unroll
    for (int r = 0; r < 4; r++) CP16(sb + so[r], Qg + go[r]);
#pragma unroll
    for (int r = 0; r < 4; r++) CP16(KV0 + so[r], Kg + go[r]);
#pragma unroll
    for (int r = 0; r < 4; r++) CP16(KV0 + 16384 + so[r], Kg + 512 + go[r]);
    CPCOMMIT(); CPWAIT0();
    __syncthreads();

    const int rowA = lane & 15;
    const uint32_t kxA = (uint32_t)(lane >> 4) * 16;
    const uint32_t swzA = (uint32_t)(rowA & 7) << 4;
    const int rowB4 = (lane & 7) | (((lane >> 4) & 1) << 3);
    const uint32_t kxB4 = (uint32_t)((lane >> 3) & 1) * 16;
    const uint32_t swzB4 = (uint32_t)(rowB4 & 7) << 4;

    uint32_t qf[4][4];
#pragma unroll
    for (int ks = 0; ks < 4; ks++)
        ldsm4(qf[ks], sb + (uint32_t)((wm0 + rowA) * 128) + (((uint32_t)(ks * 32) + kxA) ^ swzA));
    __syncthreads();

    float m0 = -1e30f, m1 = -1e30f, l0 = 0.f, l1 = 0.f;
    float oacc[8][4];
#pragma unroll
    for (int nt = 0; nt < 8; nt++)
#pragma unroll
        for (int r = 0; r < 4; r++) oacc[nt][r] = 0.f;

    const uint32_t Pw = sb + (uint32_t)wid * 4096;

    for (int kv = 0; kv < 8; kv++) {
        const uint32_t Kb = sb + 32768 + (uint32_t)(kv & 1) * 32768;
        const uint32_t Vb = Kb + 16384;

        if (kv + 1 < 8) {
            const uint32_t Kn = sb + 32768 + (uint32_t)((kv + 1) & 1) * 32768;
            const __half* Kg2 = Kg + (size_t)(kv + 1) * 128 * 1536;
#pragma unroll
            for (int r = 0; r < 4; r++) CP16(Kn + so[r], Kg2 + go[r]);
#pragma unroll
            for (int r = 0; r < 4; r++) CP16(Kn + 16384 + so[r], Kg2 + 512 + go[r]);
            CPCOMMIT();
        }

        // ---- S = Q K^T ----
        float sacc[16][4];
#pragma unroll
        for (int nt = 0; nt < 16; nt++)
#pragma unroll
            for (int r = 0; r < 4; r++) sacc[nt][r] = 0.f;
#pragma unroll
        for (int ks = 0; ks < 4; ks++) {
#pragma unroll
            for (int np = 0; np < 8; np++) {
                uint32_t bf[4];
                ldsm4(bf, Kb + (uint32_t)((np * 16 + rowB4) * 128)
                          + (((uint32_t)(ks * 32) + kxB4) ^ swzB4));
                mma16(sacc[np * 2], qf[ks], bf);
                mma16(sacc[np * 2 + 1], qf[ks], bf + 2);
            }
        }

        // ---- online softmax (FFMA-folded exp args) ----
        float r0 = -1e30f, r1 = -1e30f;
#pragma unroll
        for (int nt = 0; nt < 16; nt++) {
            r0 = fmaxf(r0, fmaxf(sacc[nt][0], sacc[nt][1]));
            r1 = fmaxf(r1, fmaxf(sacc[nt][2], sacc[nt][3]));
        }
        r0 = fmaxf(r0, __shfl_xor_sync(0xffffffffu, r0, 1));
        r0 = fmaxf(r0, __shfl_xor_sync(0xffffffffu, r0, 2));
        r1 = fmaxf(r1, __shfl_xor_sync(0xffffffffu, r1, 1));
        r1 = fmaxf(r1, __shfl_xor_sync(0xffffffffu, r1, 2));
        float mn0 = fmaxf(m0, r0), mn1 = fmaxf(m1, r1);
        float a0 = exp2f((m0 - mn0) * CEXP);
        float a1 = exp2f((m1 - mn1) * CEXP);
        m0 = mn0; m1 = mn1;
        const float mc0 = m0 * CEXP, mc1 = m1 * CEXP;
        l0 *= a0; l1 *= a1;
#pragma unroll
        for (int nt = 0; nt < 8; nt++) {
            oacc[nt][0] *= a0; oacc[nt][1] *= a0;
            oacc[nt][2] *= a1; oacc[nt][3] *= a1;
        }
#pragma unroll
        for (int nt = 0; nt < 16; nt++) {
            float p0 = exp2f(fmaf(sacc[nt][0], CEXP, -mc0));
            float p1 = exp2f(fmaf(sacc[nt][1], CEXP, -mc0));
            float p2 = exp2f(fmaf(sacc[nt][2], CEXP, -mc1));
            float p3 = exp2f(fmaf(sacc[nt][3], CEXP, -mc1));
            l0 += p0 + p1; l1 += p2 + p3;
            int t = nt * 8 + tig * 2;
            uint32_t off = (Pw - sb) + (uint32_t)(t >> 6) * 2048 + (uint32_t)(grp * 128)
                           + (((uint32_t)(t & 63) * 2) ^ ((uint32_t)grp << 4));
            *(__half2*)(sm + off)        = __floats2half2_rn(p0, p1);
            *(__half2*)(sm + off + 1024) = __floats2half2_rn(p2, p3);
        }
        __syncwarp();

        // ---- O += P V ----
#pragma unroll
        for (int kt = 0; kt < 8; kt++) {
            uint32_t pf[4];
            ldsm4(pf, Pw + (uint32_t)(kt >> 2) * 2048 + (uint32_t)(rowA * 128)
                      + (((uint32_t)((kt & 3) * 32) + kxA) ^ swzA));
#pragma unroll
            for (int np = 0; np < 4; np++) {
                uint32_t bf[4];
                ldsm4t(bf, Vb + (uint32_t)((kt * 16 + rowA) * 128)
                           + (((uint32_t)(np * 32) + ((uint32_t)(lane >> 4) * 16)) ^ swzA));
                mma16(oacc[np * 2], pf, bf);
                mma16(oacc[np * 2 + 1], pf, bf + 2);
            }
        }

        if (kv + 1 < 8) CPWAIT0();
        __syncthreads();
    }

    // ---- finalize ----
    l0 += __shfl_xor_sync(0xffffffffu, l0, 1);
    l0 += __shfl_xor_sync(0xffffffffu, l0, 2);
    l1 += __shfl_xor_sync(0xffffffffu, l1, 1);
    l1 += __shfl_xor_sync(0xffffffffu, l1, 2);
    float i0 = 1.f / l0, i1 = 1.f / l1;
    const int sg = q0 + wm0 + grp;
    size_t ob = (size_t)b * CS + (size_t)sg * 512 + h * 64 + tig * 2;
#pragma unroll
    for (int nt = 0; nt < 8; nt++) {
        float x0 = oacc[nt][0] * i0, x1 = oacc[nt][1] * i0;
        float x2 = oacc[nt][2] * i1, x3 = oacc[nt][3] * i1;
        *(float2*)(of + ob + nt * 8)            = make_float2(x0, x1);
        *(float2*)(of + ob + 8 * 512 + nt * 8)  = make_float2(x2, x3);
        *(__half2*)(oh + ob + nt * 8)           = __floats2half2_rn(x0, x1);
        *(__half2*)(oh + ob + 8 * 512 + nt * 8) = __floats2half2_rn(x2, x3);
    }
}

// ---------------------------------------------------------------------------
// fp16 GEMM (R6 configuration): 2-stage cp.async, 67584 B smem (3 CTA/SM).
// D[m,n] = epi( sum_k A[m,k]*B[n,k] ), A/B fp16 K-contig. BM=BN=128, BK=64.
// EPI: 0 QKV(fp16 out, +bias[m]); 1 INL(f32+f16 out, E+0.1*tanh(v+bias[m]));
//      2 proj(f32 out, E+v+bias[n]).
// ---------------------------------------------------------------------------
template <int EPI>
__global__ void __launch_bounds__(256) mm16_kernel(
    const __half* __restrict__ Abase, int ldA, size_t sAo,
    const __half* __restrict__ Bbase, int ldB, size_t sBo,
    float* __restrict__ O32, __half* __restrict__ O16, int ldO, size_t sOo,
    const float* __restrict__ bias,
    const float* __restrict__ Ebase, size_t sEo,
    int K)
{
    constexpr int ABYTES = 16384;       // 128 x 64 halves
    constexpr int STAGE  = 32768;
    constexpr int PITCH  = 132;

    extern __shared__ char smemc[];
    const uint32_t sb = smem_u32(smemc);
    const int tid = threadIdx.x;
    const int wid = tid >> 5;
    const int lane = tid & 31;
    const int grp = lane >> 2, tig = lane & 3;

    const int z = blockIdx.z;
    const __half* Ag = Abase + (size_t)z * sAo;
    const __half* Bg = Bbase + (size_t)z * sBo;
    const float*  E  = (EPI != 0) ? (Ebase + (size_t)z * sEo) : nullptr;

    const int m0 = blockIdx.y * 128;
    const int n0 = blockIdx.x * 128;
    const int wm0 = (wid & 1) * 64;
    const int wn0 = (wid >> 1) * 32;

    uint32_t asw[4];
    size_t ago[4], bgo[4];
#pragma unroll
    for (int r = 0; r < 4; r++) {
        int li = tid + r * 256;
        int row = li >> 3, c8 = li & 7;
        asw[r] = (uint32_t)(row * 128 + c8 * 16) ^ ((uint32_t)(row & 7) << 4);
        ago[r] = (size_t)(m0 + row) * ldA + c8 * 8;
        bgo[r] = (size_t)(n0 + row) * ldB + c8 * 8;
    }

    const int rowA = lane & 15;
    const uint32_t kxA = (uint32_t)(lane >> 4) * 16;
    const uint32_t swzA = (uint32_t)(rowA & 7) << 4;
    const int rowB4 = (lane & 7) | (((lane >> 4) & 1) << 3);
    const uint32_t kxB4 = (uint32_t)((lane >> 3) & 1) * 16;
    const uint32_t swzB4 = (uint32_t)(rowB4 & 7) << 4;

    float acc[4][4][4];
#pragma unroll
    for (int mt = 0; mt < 4; mt++)
#pragma unroll
        for (int nt = 0; nt < 4; nt++)
#pragma unroll
            for (int r = 0; r < 4; r++) acc[mt][nt][r] = 0.f;

    const int nkt = K >> 6;

    // prologue: tile 0
#pragma unroll
    for (int r = 0; r < 4; r++) { CP16(sb + asw[r], Ag + ago[r]); CP16(sb + ABYTES + asw[r], Bg + bgo[r]); }
    CPCOMMIT(); CPWAIT0();
    __syncthreads();

    for (int kt = 0; kt < nkt; kt++) {
        const int cur = kt & 1;
        const uint32_t As = sb + cur * STAGE;
        const uint32_t Bs = As + ABYTES;

        if (kt + 1 < nkt) {
            const uint32_t nb = sb + (cur ^ 1) * STAGE;
            const int k0 = (kt + 1) << 6;
#pragma unroll
            for (int r = 0; r < 4; r++) { CP16(nb + asw[r], Ag + ago[r] + k0); CP16(nb + ABYTES + asw[r], Bg + bgo[r] + k0); }
            CPCOMMIT();
        }

#pragma unroll
        for (int ks = 0; ks < 4; ks++) {
            uint32_t afr[4][4];
#pragma unroll
            for (int mt = 0; mt < 4; mt++)
                ldsm4(afr[mt], As + (uint32_t)((wm0 + mt * 16 + rowA) * 128)
                              + (((uint32_t)(ks * 32) + kxA) ^ swzA));
            uint32_t bfr[2][4];
#pragma unroll
            for (int np = 0; np < 2; np++)
                ldsm4(bfr[np], Bs + (uint32_t)((wn0 + np * 16 + rowB4) * 128)
                              + (((uint32_t)(ks * 32) + kxB4) ^ swzB4));
#pragma unroll
            for (int mt = 0; mt < 4; mt++)
#pragma unroll
                for (int np = 0; np < 2; np++) {
                    mma16(acc[mt][np * 2], afr[mt], bfr[np]);
                    mma16(acc[mt][np * 2 + 1], afr[mt], bfr[np] + 2);
                }
        }

        if (kt + 1 < nkt) { CPWAIT0(); __syncthreads(); }
    }

    // ---- epilogue: transpose through SMEM ([n][m] fp32) ----
    __syncthreads();
    float* Csm = (float*)smemc;
#pragma unroll
    for (int mt = 0; mt < 4; mt++) {
#pragma unroll
        for (int nt = 0; nt < 4; nt++) {
            int m = wm0 + mt * 16 + grp;
            int n = wn0 + nt * 8 + tig * 2;
            Csm[(n)     * PITCH + m]     = acc[mt][nt][0];
            Csm[(n + 1) * PITCH + m]     = acc[mt][nt][1];
            Csm[(n)     * PITCH + m + 8] = acc[mt][nt][2];
            Csm[(n + 1) * PITCH + m + 8] = acc[mt][nt][3];
        }
    }
    __syncthreads();

#pragma unroll
    for (int it = 0; it < 16; it++) {
        int li = tid + it * 256;
        int n = li >> 5, m4 = (li & 31) << 2;
        float4 c = *(float4*)(Csm + n * PITCH + m4);
        size_t idx = (size_t)z * sOo + (size_t)(n0 + n) * ldO + m0 + m4;
        if (EPI == 0) {
            float4 bm = *(const float4*)(bias + m0 + m4);
            union { __half2 h[2]; uint2 u; } pk;
            pk.h[0] = __floats2half2_rn(c.x + bm.x, c.y + bm.y);
            pk.h[1] = __floats2half2_rn(c.z + bm.z, c.w + bm.w);
            *(uint2*)(O16 + idx) = pk.u;
        } else if (EPI == 1) {
            float4 bm = *(const float4*)(bias + m0 + m4);
            float4 e = *(const float4*)(E + (size_t)(n0 + n) * ldO + m0 + m4);
            float4 r;
            r.x = e.x + 0.1f * tanhf(c.x + bm.x);
            r.y = e.y + 0.1f * tanhf(c.y + bm.y);
            r.z = e.z + 0.1f * tanhf(c.z + bm.z);
            r.w = e.w + 0.1f * tanhf(c.w + bm.w);
            *(float4*)(O32 + idx) = r;
            union { __half2 h[2]; uint2 u; } pk;
            pk.h[0] = __floats2half2_rn(r.x, r.y);
            pk.h[1] = __floats2half2_rn(r.z, r.w);
            *(uint2*)(O16 + idx) = pk.u;
        } else {
            float bn = bias[n0 + n];
            float4 e = *(const float4*)(E + (size_t)(n0 + n) * ldO + m0 + m4);
            c.x += e.x + bn; c.y += e.y + bn; c.z += e.z + bn; c.w += e.w + bn;
            *(float4*)(O32 + idx) = c;
        }
    }
}

// ---------------------------------------------------------------------------
// Host launcher
// ---------------------------------------------------------------------------
extern "C" void kernel_launch(void* const* d_in, const int* in_sizes, int n_in,
                              void* d_out, int out_size) {
    const float* x        = (const float*)d_in[0];
    const float* gn_scale = (const float*)d_in[1];
    const float* gn_bias  = (const float*)d_in[2];
    const float* qkv_w    = (const float*)d_in[3];
    const float* qkv_b    = (const float*)d_in[4];
    const float* proj_w   = (const float*)d_in[5];
    const float* proj_b   = (const float*)d_in[6];
    const float* inl_w    = (const float*)d_in[7];
    const float* inl_b    = (const float*)d_in[8];
    float* out = (float*)d_out;

    __half *hgn, *qkvT, *h1h, *h2h, *w16;
    float *h1f, *h2f, *stats;
    float2* part;
    cudaGetSymbolAddress((void**)&hgn,   g_hgn);
    cudaGetSymbolAddress((void**)&qkvT,  g_qkvT);
    cudaGetSymbolAddress((void**)&h1f,   g_h1f);
    cudaGetSymbolAddress((void**)&h1h,   g_h1h);
    cudaGetSymbolAddress((void**)&h2f,   g_h2f);
    cudaGetSymbolAddress((void**)&h2h,   g_h2h);
    cudaGetSymbolAddress((void**)&w16,   g_w16);
    cudaGetSymbolAddress((void**)&stats, g_stats);
    cudaGetSymbolAddress((void**)&part,  g_part);

    const int SMMM = 132 * 128 * 4;   // 67584 (>= 2*32768) -> 3 CTA/SM
    const int SMFL = 98304;
    cudaFuncSetAttribute(mm16_kernel<0>, cudaFuncAttributeMaxDynamicSharedMemorySize, SMMM);
    cudaFuncSetAttribute(mm16_kernel<1>, cudaFuncAttributeMaxDynamicSharedMemorySize, SMMM);
    cudaFuncSetAttribute(mm16_kernel<2>, cudaFuncAttributeMaxDynamicSharedMemorySize, SMMM);
    cudaFuncSetAttribute(flash_kernel,   cudaFuncAttributeMaxDynamicSharedMemorySize, SMFL);

    const size_t CSz = (size_t)CS;

    // 0) weights->fp16 + GN partial stats (merged)
    prep_kernel<<<1152, 256>>>(qkv_w, inl_w, proj_w, w16, x, part);
    gn_stats_b_kernel<<<1, 512>>>(part, stats);
    gn_apply_t_kernel<<<dim3(32, 8, B_), dim3(32, 8)>>>(x, stats, gn_scale, gn_bias, hgn);

    // 1) QKV
    mm16_kernel<0><<<dim3(8, 12, B_), 256, SMMM>>>(
        w16, C_, 0,
        hgn, C_, CSz,
        nullptr, qkvT, 1536, (size_t)S_ * 1536,
        qkv_b, nullptr, 0, C_);

    // 2) fused attention -> h1 (f32 + f16)
    flash_kernel<<<dim3(8, 1, B_ * NH), 256, SMFL>>>(qkvT, h1f, h1h);

    // 3) INL x3
    const float* srcf = h1f; const __half* srch = h1h;
    float* dstf = h2f; __half* dsth = h2h;
    for (int it = 0; it < 3; it++) {
        mm16_kernel<1><<<dim3(8, 4, B_), 256, SMMM>>>(
            w16 + 786432, C_, 0,
            srch, C_, CSz,
            dstf, dsth, C_, CSz,
            inl_b, srcf, CSz, C_);
        const float* tf = srcf; srcf = dstf; dstf = (float*)tf;
        const __half* th = srch; srch = dsth; dsth = (__half*)th;
    }

    // 4) proj + residual
    mm16_kernel<2><<<dim3(4, 8, B_), 256, SMMM>>>(
        srch, C_, CSz,
        w16 + 1048576, C_, 0,
        out, nullptr, S_, CSz,
        proj_b, x, CSz, C_);
}

// round 15
// speedup vs baseline: 1.4644x; 1.4644x over previous
#include <cuda_runtime.h>
#include <cuda_fp16.h>
#include <cstdint>
#include <cstddef>

// ===========================================================================
// INLAttentionBlock, fp16 tensor-core pipeline (mma.sync m16n8k16, f32 accum):
// GN+T -> QKV -> flash(QK+softmax+PV) -> 3x INL -> proj+res
// B=8, C=512, S=1024, nh=8, hd=64. Activations token-major [b, s, c].
// MMA operands fp16; residual/Euler state kept in fp32 shadows.
// ===========================================================================

#define B_ 8
#define C_ 512
#define S_ 1024
#define NH 8
#define CS (C_ * S_)
#define CEXP 0.18033688011112042f   // 0.125 * log2(e)

__device__ __half g_hgn[(size_t)B_ * S_ * C_];        // [b, s, c] fp16
__device__ __half g_qkvT[(size_t)B_ * S_ * 1536];     // [b, s, 3C] fp16
__device__ float  g_h1f[(size_t)B_ * S_ * C_];        // fp32 shadow
__device__ __half g_h1h[(size_t)B_ * S_ * C_];
__device__ float  g_h2f[(size_t)B_ * S_ * C_];
__device__ __half g_h2h[(size_t)B_ * S_ * C_];
__device__ __half g_w16[1310720];                     // qkv|inl|proj fp16 weights
__device__ float  g_stats[2 * B_ * NH];
__device__ float2 g_part[512];

// ---------------------------------------------------------------------------
// helpers
// ---------------------------------------------------------------------------
__device__ __forceinline__ uint32_t smem_u32(const void* p) {
    uint32_t a;
    asm("{ .reg .u64 t; cvta.to.shared.u64 t, %1; cvt.u32.u64 %0, t; }" : "=r"(a) : "l"(p));
    return a;
}
__device__ __forceinline__ void ldsm4(uint32_t* r, uint32_t addr) {
    asm volatile("ldmatrix.sync.aligned.m8n8.x4.shared.b16 {%0,%1,%2,%3}, [%4];"
                 : "=r"(r[0]), "=r"(r[1]), "=r"(r[2]), "=r"(r[3]) : "r"(addr));
}
__device__ __forceinline__ void ldsm4t(uint32_t* r, uint32_t addr) {
    asm volatile("ldmatrix.sync.aligned.m8n8.x4.trans.shared.b16 {%0,%1,%2,%3}, [%4];"
                 : "=r"(r[0]), "=r"(r[1]), "=r"(r[2]), "=r"(r[3]) : "r"(addr));
}
__device__ __forceinline__ void ldsm2(uint32_t* r, uint32_t addr) {
    asm volatile("ldmatrix.sync.aligned.m8n8.x2.shared.b16 {%0,%1}, [%2];"
                 : "=r"(r[0]), "=r"(r[1]) : "r"(addr));
}
__device__ __forceinline__ void mma16(float* d, const uint32_t* a, const uint32_t* b) {
    asm volatile("mma.sync.aligned.m16n8k16.row.col.f32.f16.f16.f32 "
                 "{%0,%1,%2,%3}, {%4,%5,%6,%7}, {%8,%9}, {%0,%1,%2,%3};"
                 : "+f"(d[0]), "+f"(d[1]), "+f"(d[2]), "+f"(d[3])
                 : "r"(a[0]), "r"(a[1]), "r"(a[2]), "r"(a[3]), "r"(b[0]), "r"(b[1]));
}
#define CP16(sa, ga) asm volatile("cp.async.cg.shared.global [%0], [%1], 16;" :: "r"(sa), "l"((const void*)(ga)))
#define CPCOMMIT()   asm volatile("cp.async.commit_group;" ::: "memory")
#define CPWAIT0()    asm volatile("cp.async.wait_group 0;" ::: "memory")

// ---------------------------------------------------------------------------
// weights fp32 -> fp16, single launch (blocks 0-383 qkv, 384-511 inl, 512-639 proj)
// ---------------------------------------------------------------------------
__global__ void f2h_all_kernel(const float* __restrict__ qkv_w,
                               const float* __restrict__ inl_w,
                               const float* __restrict__ proj_w,
                               __half* __restrict__ d) {
    int bb = blockIdx.x;
    const float* s;
    int base;
    if (bb < 384)      { s = qkv_w;  base = bb * 2048; }
    else if (bb < 512) { s = inl_w;  base = (bb - 384) * 2048; d += 786432; }
    else               { s = proj_w; base = (bb - 512) * 2048; d += 1048576; }
    int i = base + threadIdx.x * 8;
    float4 a = *(const float4*)(s + i);
    float4 b = *(const float4*)(s + i + 4);
    union { __half2 h[4]; uint4 u; } pk;
    pk.h[0] = __floats2half2_rn(a.x, a.y);
    pk.h[1] = __floats2half2_rn(a.z, a.w);
    pk.h[2] = __floats2half2_rn(b.x, b.y);
    pk.h[3] = __floats2half2_rn(b.z, b.w);
    *(uint4*)(d + i) = pk.u;
}

// ---------------------------------------------------------------------------
// GroupNorm stats, two-stage (512 partial CTAs -> 1 reduce CTA)
// ---------------------------------------------------------------------------
__global__ void gn_stats_a_kernel(const float* __restrict__ x, float2* __restrict__ part) {
    __shared__ float sh[256], sh2[256];
    const int tid = threadIdx.x;
    const float4* p = (const float4*)(x + (size_t)blockIdx.x * 8192);
    float s = 0.f, s2 = 0.f;
#pragma unroll
    for (int r = 0; r < 8; r++) {
        float4 v = p[tid + r * 256];
        s  += v.x + v.y + v.z + v.w;
        s2 += v.x * v.x + v.y * v.y + v.z * v.z + v.w * v.w;
    }
    sh[tid] = s; sh2[tid] = s2;
    __syncthreads();
    for (int st = 128; st > 0; st >>= 1) {
        if (tid < st) { sh[tid] += sh[tid + st]; sh2[tid] += sh2[tid + st]; }
        __syncthreads();
    }
    if (tid == 0) part[blockIdx.x] = make_float2(sh[0], sh2[0]);
}

__global__ void gn_stats_b_kernel(const float2* __restrict__ part, float* __restrict__ stats) {
    const int t = threadIdx.x;   // 512
    float2 p = part[t];
    float s = p.x, s2 = p.y;
#pragma unroll
    for (int o = 4; o > 0; o >>= 1) {
        s  += __shfl_down_sync(0xffffffffu, s,  o, 8);
        s2 += __shfl_down_sync(0xffffffffu, s2, o, 8);
    }
    if ((t & 7) == 0) {
        int g = t >> 3;
        float mean = s * (1.f / 65536.f);
        float var  = s2 * (1.f / 65536.f) - mean * mean;
        stats[2 * g]     = mean;
        stats[2 * g + 1] = rsqrtf(var + 1e-5f);
    }
}

__global__ void gn_apply_t_kernel(const float* __restrict__ x, const float* __restrict__ stats,
                                  const float* __restrict__ sc, const float* __restrict__ bi,
                                  __half* __restrict__ hgn) {
    __shared__ float t[32][33];
    const int b = blockIdx.z;
    const int c0 = blockIdx.y * 32;
    const int s0 = blockIdx.x * 32;
    const int tx = threadIdx.x, ty = threadIdx.y;
#pragma unroll
    for (int r = 0; r < 4; r++) {
        int c = c0 + ty + r * 8;
        int bg = b * 8 + (c >> 6);
        float mean = stats[2 * bg], rstd = stats[2 * bg + 1];
        float a = rstd * sc[c];
        float bb = bi[c] - mean * a;
        t[ty + r * 8][tx] = x[(size_t)b * CS + (size_t)c * S_ + s0 + tx] * a + bb;
    }
    __syncthreads();
#pragma unroll
    for (int r = 0; r < 4; r++) {
        int s = s0 + ty + r * 8;
        hgn[(size_t)b * CS + (size_t)s * C_ + c0 + tx] = __float2half_rn(t[tx][ty + r * 8]);
    }
}

// ---------------------------------------------------------------------------
// Flash attention fp16: CTA = (b,h, 128 q rows). 256 thr / 8 warps.
// SMEM: [0,32K) warp P slices (Q staged in [0,16K) first),
//       [32K,64K) K0|V0, [64K,96K) K1|V1. K,V tiles: [t(128) x 64h] 128B rows.
// ---------------------------------------------------------------------------
__global__ void __launch_bounds__(256, 1) flash_kernel(
    const __half* __restrict__ qkvT, float* __restrict__ of, __half* __restrict__ oh)
{
    extern __shared__ char sm[];
    const uint32_t sb = smem_u32(sm);
    const int tid = threadIdx.x, wid = tid >> 5, lane = tid & 31;
    const int grp = lane >> 2, tig = lane & 3;
    const int b = blockIdx.z >> 3, h = blockIdx.z & 7;
    const int q0 = blockIdx.x * 128;
    const int wm0 = wid * 16;

    const __half* Qg = qkvT + (size_t)b * S_ * 1536 + (size_t)q0 * 1536 + h * 64;
    const __half* Kg = qkvT + (size_t)b * S_ * 1536 + 512 + h * 64;

    uint32_t so[4]; int go[4];
#pragma unroll
    for (int r = 0; r < 4; r++) {
        int li = tid + r * 256;
        int row = li >> 3, c8 = li & 7;
        so[r] = (uint32_t)(row * 128 + c8 * 16) ^ ((uint32_t)(row & 7) << 4);
        go[r] = row * 1536 + c8 * 8;
    }

    const uint32_t KV0 = sb + 32768;
#pragma unroll
    for (int r = 0; r < 4; r++) CP16(sb + so[r], Qg + go[r]);
#pragma unroll
    for (int r = 0; r < 4; r++) CP16(KV0 + so[r], Kg + go[r]);
#pragma unroll
    for (int r = 0; r < 4; r++) CP16(KV0 + 16384 + so[r], Kg + 512 + go[r]);
    CPCOMMIT(); CPWAIT0();
    __syncthreads();

    const int rowA = lane & 15;
    const uint32_t kxA = (uint32_t)(lane >> 4) * 16;
    const uint32_t swzA = (uint32_t)(rowA & 7) << 4;
    const int rowB4 = (lane & 7) | (((lane >> 4) & 1) << 3);
    const uint32_t kxB4 = (uint32_t)((lane >> 3) & 1) * 16;
    const uint32_t swzB4 = (uint32_t)(rowB4 & 7) << 4;

    uint32_t qf[4][4];
#pragma unroll
    for (int ks = 0; ks < 4; ks++)
        ldsm4(qf[ks], sb + (uint32_t)((wm0 + rowA) * 128) + (((uint32_t)(ks * 32) + kxA) ^ swzA));
    __syncthreads();

    float m0 = -1e30f, m1 = -1e30f, l0 = 0.f, l1 = 0.f;
    float oacc[8][4];
#pragma unroll
    for (int nt = 0; nt < 8; nt++)
#pragma unroll
        for (int r = 0; r < 4; r++) oacc[nt][r] = 0.f;

    const uint32_t Pw = sb + (uint32_t)wid * 4096;

    for (int kv = 0; kv < 8; kv++) {
        const uint32_t Kb = sb + 32768 + (uint32_t)(kv & 1) * 32768;
        const uint32_t Vb = Kb + 16384;

        if (kv + 1 < 8) {
            const uint32_t Kn = sb + 32768 + (uint32_t)((kv + 1) & 1) * 32768;
            const __half* Kg2 = Kg + (size_t)(kv + 1) * 128 * 1536;
#pragma unroll
            for (int r = 0; r < 4; r++) CP16(Kn + so[r], Kg2 + go[r]);
#pragma unroll
            for (int r = 0; r < 4; r++) CP16(Kn + 16384 + so[r], Kg2 + 512 + go[r]);
            CPCOMMIT();
        }

        // ---- S = Q K^T ----
        float sacc[16][4];
#pragma unroll
        for (int nt = 0; nt < 16; nt++)
#pragma unroll
            for (int r = 0; r < 4; r++) sacc[nt][r] = 0.f;
#pragma unroll
        for (int ks = 0; ks < 4; ks++) {
#pragma unroll
            for (int np = 0; np < 8; np++) {
                uint32_t bf[4];
                ldsm4(bf, Kb + (uint32_t)((np * 16 + rowB4) * 128)
                          + (((uint32_t)(ks * 32) + kxB4) ^ swzB4));
                mma16(sacc[np * 2], qf[ks], bf);
                mma16(sacc[np * 2 + 1], qf[ks], bf + 2);
            }
        }

        // ---- online softmax ----
        float r0 = -1e30f, r1 = -1e30f;
#pragma unroll
        for (int nt = 0; nt < 16; nt++) {
            r0 = fmaxf(r0, fmaxf(sacc[nt][0], sacc[nt][1]));
            r1 = fmaxf(r1, fmaxf(sacc[nt][2], sacc[nt][3]));
        }
        r0 = fmaxf(r0, __shfl_xor_sync(0xffffffffu, r0, 1));
        r0 = fmaxf(r0, __shfl_xor_sync(0xffffffffu, r0, 2));
        r1 = fmaxf(r1, __shfl_xor_sync(0xffffffffu, r1, 1));
        r1 = fmaxf(r1, __shfl_xor_sync(0xffffffffu, r1, 2));
        float mn0 = fmaxf(m0, r0), mn1 = fmaxf(m1, r1);
        float a0 = exp2f((m0 - mn0) * CEXP);
        float a1 = exp2f((m1 - mn1) * CEXP);
        m0 = mn0; m1 = mn1;
        l0 *= a0; l1 *= a1;
#pragma unroll
        for (int nt = 0; nt < 8; nt++) {
            oacc[nt][0] *= a0; oacc[nt][1] *= a0;
            oacc[nt][2] *= a1; oacc[nt][3] *= a1;
        }
#pragma unroll
        for (int nt = 0; nt < 16; nt++) {
            float p0 = exp2f((sacc[nt][0] - m0) * CEXP);
            float p1 = exp2f((sacc[nt][1] - m0) * CEXP);
            float p2 = exp2f((sacc[nt][2] - m1) * CEXP);
            float p3 = exp2f((sacc[nt][3] - m1) * CEXP);
            l0 += p0 + p1; l1 += p2 + p3;
            int t = nt * 8 + tig * 2;
            uint32_t off = (Pw - sb) + (uint32_t)(t >> 6) * 2048 + (uint32_t)(grp * 128)
                           + (((uint32_t)(t & 63) * 2) ^ ((uint32_t)grp << 4));
            *(__half2*)(sm + off)        = __floats2half2_rn(p0, p1);
            *(__half2*)(sm + off + 1024) = __floats2half2_rn(p2, p3);
        }
        __syncwarp();

        // ---- O += P V ----
#pragma unroll
        for (int kt = 0; kt < 8; kt++) {
            uint32_t pf[4];
            ldsm4(pf, Pw + (uint32_t)(kt >> 2) * 2048 + (uint32_t)(rowA * 128)
                      + (((uint32_t)((kt & 3) * 32) + kxA) ^ swzA));
#pragma unroll
            for (int np = 0; np < 4; np++) {
                uint32_t bf[4];
                ldsm4t(bf, Vb + (uint32_t)((kt * 16 + rowA) * 128)
                           + (((uint32_t)(np * 32) + ((uint32_t)(lane >> 4) * 16)) ^ swzA));
                mma16(oacc[np * 2], pf, bf);
                mma16(oacc[np * 2 + 1], pf, bf + 2);
            }
        }

        if (kv + 1 < 8) CPWAIT0();
        __syncthreads();
    }

    // ---- finalize ----
    l0 += __shfl_xor_sync(0xffffffffu, l0, 1);
    l0 += __shfl_xor_sync(0xffffffffu, l0, 2);
    l1 += __shfl_xor_sync(0xffffffffu, l1, 1);
    l1 += __shfl_xor_sync(0xffffffffu, l1, 2);
    float i0 = 1.f / l0, i1 = 1.f / l1;
    const int sg = q0 + wm0 + grp;
    size_t ob = (size_t)b * CS + (size_t)sg * 512 + h * 64 + tig * 2;
#pragma unroll
    for (int nt = 0; nt < 8; nt++) {
        float x0 = oacc[nt][0] * i0, x1 = oacc[nt][1] * i0;
        float x2 = oacc[nt][2] * i1, x3 = oacc[nt][3] * i1;
        *(float2*)(of + ob + nt * 8)            = make_float2(x0, x1);
        *(float2*)(of + ob + 8 * 512 + nt * 8)  = make_float2(x2, x3);
        *(__half2*)(oh + ob + nt * 8)           = __floats2half2_rn(x0, x1);
        *(__half2*)(oh + ob + 8 * 512 + nt * 8) = __floats2half2_rn(x2, x3);
    }
}

// ---------------------------------------------------------------------------
// fp16 GEMM: D[m,n] = epi( sum_k A[m,k]*B[n,k] ), A/B fp16 K-contig.
// BM=128, BN=128, BK=64. EPI: 0 QKV(out fp16, +bias[m]);
// 1 INL(out f32+f16, E + 0.1*tanh(v+bias[m])); 2 proj(out f32, E + v + bias[n]).
// ---------------------------------------------------------------------------
template <int EPI>
__global__ void __launch_bounds__(256) mm16_kernel(
    const __half* __restrict__ Abase, int ldA, size_t sAo,
    const __half* __restrict__ Bbase, int ldB, size_t sBo,
    float* __restrict__ O32, __half* __restrict__ O16, int ldO, size_t sOo,
    const float* __restrict__ bias,
    const float* __restrict__ Ebase, size_t sEo,
    int K)
{
    constexpr int ABYTES = 16384;       // 128 x 64 halves
    constexpr int STAGE  = 32768;
    constexpr int PITCH  = 132;

    extern __shared__ char smemc[];
    const uint32_t sb = smem_u32(smemc);
    const int tid = threadIdx.x;
    const int wid = tid >> 5;
    const int lane = tid & 31;
    const int grp = lane >> 2, tig = lane & 3;

    const int z = blockIdx.z;
    const __half* Ag = Abase + (size_t)z * sAo;
    const __half* Bg = Bbase + (size_t)z * sBo;
    const float*  E  = (EPI != 0) ? (Ebase + (size_t)z * sEo) : nullptr;

    const int m0 = blockIdx.y * 128;
    const int n0 = blockIdx.x * 128;
    const int wm0 = (wid & 1) * 64;
    const int wn0 = (wid >> 1) * 32;

    uint32_t asw[4];
    size_t ago[4], bgo[4];
#pragma unroll
    for (int r = 0; r < 4; r++) {
        int li = tid + r * 256;
        int row = li >> 3, c8 = li & 7;
        asw[r] = (uint32_t)(row * 128 + c8 * 16) ^ ((uint32_t)(row & 7) << 4);
        ago[r] = (size_t)(m0 + row) * ldA + c8 * 8;
        bgo[r] = (size_t)(n0 + row) * ldB + c8 * 8;
    }

    const int rowA = lane & 15;
    const uint32_t kxA = (uint32_t)(lane >> 4) * 16;
    const uint32_t swzA = (uint32_t)(rowA & 7) << 4;
    const int rowB4 = (lane & 7) | (((lane >> 4) & 1) << 3);
    const uint32_t kxB4 = (uint32_t)((lane >> 3) & 1) * 16;
    const uint32_t swzB4 = (uint32_t)(rowB4 & 7) << 4;

    float acc[4][4][4];
#pragma unroll
    for (int mt = 0; mt < 4; mt++)
#pragma unroll
        for (int nt = 0; nt < 4; nt++)
#pragma unroll
            for (int r = 0; r < 4; r++) acc[mt][nt][r] = 0.f;

    const int nkt = K >> 6;

    // prologue: tile 0
#pragma unroll
    for (int r = 0; r < 4; r++) { CP16(sb + asw[r], Ag + ago[r]); CP16(sb + ABYTES + asw[r], Bg + bgo[r]); }
    CPCOMMIT(); CPWAIT0();
    __syncthreads();

    for (int kt = 0; kt < nkt; kt++) {
        const int cur = kt & 1;
        const uint32_t As = sb + cur * STAGE;
        const uint32_t Bs = As + ABYTES;

        if (kt + 1 < nkt) {
            const uint32_t nb = sb + (cur ^ 1) * STAGE;
            const int k0 = (kt + 1) << 6;
#pragma unroll
            for (int r = 0; r < 4; r++) { CP16(nb + asw[r], Ag + ago[r] + k0); CP16(nb + ABYTES + asw[r], Bg + bgo[r] + k0); }
            CPCOMMIT();
        }

#pragma unroll
        for (int ks = 0; ks < 4; ks++) {
            uint32_t afr[4][4];
#pragma unroll
            for (int mt = 0; mt < 4; mt++)
                ldsm4(afr[mt], As + (uint32_t)((wm0 + mt * 16 + rowA) * 128)
                              + (((uint32_t)(ks * 32) + kxA) ^ swzA));
            uint32_t bfr[2][4];
#pragma unroll
            for (int np = 0; np < 2; np++)
                ldsm4(bfr[np], Bs + (uint32_t)((wn0 + np * 16 + rowB4) * 128)
                              + (((uint32_t)(ks * 32) + kxB4) ^ swzB4));
#pragma unroll
            for (int mt = 0; mt < 4; mt++)
#pragma unroll
                for (int np = 0; np < 2; np++) {
                    mma16(acc[mt][np * 2], afr[mt], bfr[np]);
                    mma16(acc[mt][np * 2 + 1], afr[mt], bfr[np] + 2);
                }
        }

        if (kt + 1 < nkt) { CPWAIT0(); __syncthreads(); }
    }

    // ---- epilogue: transpose through SMEM ([n][m] fp32) ----
    __syncthreads();
    float* Csm = (float*)smemc;
#pragma unroll
    for (int mt = 0; mt < 4; mt++) {
#pragma unroll
        for (int nt = 0; nt < 4; nt++) {
            int m = wm0 + mt * 16 + grp;
            int n = wn0 + nt * 8 + tig * 2;
            Csm[(n)     * PITCH + m]     = acc[mt][nt][0];
            Csm[(n + 1) * PITCH + m]     = acc[mt][nt][1];
            Csm[(n)     * PITCH + m + 8] = acc[mt][nt][2];
            Csm[(n + 1) * PITCH + m + 8] = acc[mt][nt][3];
        }
    }
    __syncthreads();

#pragma unroll
    for (int it = 0; it < 16; it++) {
        int li = tid + it * 256;
        int n = li >> 5, m4 = (li & 31) << 2;
        float4 c = *(float4*)(Csm + n * PITCH + m4);
        size_t idx = (size_t)z * sOo + (size_t)(n0 + n) * ldO + m0 + m4;
        if (EPI == 0) {
            float4 bm = *(const float4*)(bias + m0 + m4);
            union { __half2 h[2]; uint2 u; } pk;
            pk.h[0] = __floats2half2_rn(c.x + bm.x, c.y + bm.y);
            pk.h[1] = __floats2half2_rn(c.z + bm.z, c.w + bm.w);
            *(uint2*)(O16 + idx) = pk.u;
        } else if (EPI == 1) {
            float4 bm = *(const float4*)(bias + m0 + m4);
            float4 e = *(const float4*)(E + (size_t)(n0 + n) * ldO + m0 + m4);
            float4 r;
            r.x = e.x + 0.1f * tanhf(c.x + bm.x);
            r.y = e.y + 0.1f * tanhf(c.y + bm.y);
            r.z = e.z + 0.1f * tanhf(c.z + bm.z);
            r.w = e.w + 0.1f * tanhf(c.w + bm.w);
            *(float4*)(O32 + idx) = r;
            union { __half2 h[2]; uint2 u; } pk;
            pk.h[0] = __floats2half2_rn(r.x, r.y);
            pk.h[1] = __floats2half2_rn(r.z, r.w);
            *(uint2*)(O16 + idx) = pk.u;
        } else {
            float bn = bias[n0 + n];
            float4 e = *(const float4*)(E + (size_t)(n0 + n) * ldO + m0 + m4);
            c.x += e.x + bn; c.y += e.y + bn; c.z += e.z + bn; c.w += e.w + bn;
            *(float4*)(O32 + idx) = c;
        }
    }
}

// ---------------------------------------------------------------------------
// Host launcher
// ---------------------------------------------------------------------------
extern "C" void kernel_launch(void* const* d_in, const int* in_sizes, int n_in,
                              void* d_out, int out_size) {
    const float* x        = (const float*)d_in[0];
    const float* gn_scale = (const float*)d_in[1];
    const float* gn_bias  = (const float*)d_in[2];
    const float* qkv_w    = (const float*)d_in[3];
    const float* qkv_b    = (const float*)d_in[4];
    const float* proj_w   = (const float*)d_in[5];
    const float* proj_b   = (const float*)d_in[6];
    const float* inl_w    = (const float*)d_in[7];
    const float* inl_b    = (const float*)d_in[8];
    float* out = (float*)d_out;

    __half *hgn, *qkvT, *h1h, *h2h, *w16;
    float *h1f, *h2f, *stats;
    float2* part;
    cudaGetSymbolAddress((void**)&hgn,   g_hgn);
    cudaGetSymbolAddress((void**)&qkvT,  g_qkvT);
    cudaGetSymbolAddress((void**)&h1f,   g_h1f);
    cudaGetSymbolAddress((void**)&h1h,   g_h1h);
    cudaGetSymbolAddress((void**)&h2f,   g_h2f);
    cudaGetSymbolAddress((void**)&h2h,   g_h2h);
    cudaGetSymbolAddress((void**)&w16,   g_w16);
    cudaGetSymbolAddress((void**)&stats, g_stats);
    cudaGetSymbolAddress((void**)&part,  g_part);

    const int SMMM = 132 * 128 * 4;   // 67584 (>= 2*32768)
    const int SMFL = 98304;
    cudaFuncSetAttribute(mm16_kernel<0>, cudaFuncAttributeMaxDynamicSharedMemorySize, SMMM);
    cudaFuncSetAttribute(mm16_kernel<1>, cudaFuncAttributeMaxDynamicSharedMemorySize, SMMM);
    cudaFuncSetAttribute(mm16_kernel<2>, cudaFuncAttributeMaxDynamicSharedMemorySize, SMMM);
    cudaFuncSetAttribute(flash_kernel,   cudaFuncAttributeMaxDynamicSharedMemorySize, SMFL);

    const size_t CSz = (size_t)CS;

    // 0) weights -> fp16 (single launch)
    f2h_all_kernel<<<640, 256>>>(qkv_w, inl_w, proj_w, w16);

    // 1) GroupNorm (two-stage stats + apply/transpose)
    gn_stats_a_kernel<<<512, 256>>>(x, part);
    gn_stats_b_kernel<<<1, 512>>>(part, stats);
    gn_apply_t_kernel<<<dim3(32, 16, B_), dim3(32, 8)>>>(x, stats, gn_scale, gn_bias, hgn);

    // 2) QKV: qkvT[s,o] fp16 = qkv_w[o,:].hgn[s,:] + qkv_b[o]   (m=o, n=s)
    mm16_kernel<0><<<dim3(8, 12, B_), 256, SMMM>>>(
        w16, C_, 0,
        hgn, C_, CSz,
        nullptr, qkvT, 1536, (size_t)S_ * 1536,
        qkv_b, nullptr, 0, C_);

    // 3) fused attention -> h1 (f32 + f16)
    flash_kernel<<<dim3(8, 1, B_ * NH), 256, SMFL>>>(qkvT, h1f, h1h);

    // 4) INL x3
    const float* srcf = h1f; const __half* srch = h1h;
    float* dstf = h2f; __half* dsth = h2h;
    for (int it = 0; it < 3; it++) {
        mm16_kernel<1><<<dim3(8, 4, B_), 256, SMMM>>>(
            w16 + 786432, C_, 0,
            srch, C_, CSz,
            dstf, dsth, C_, CSz,
            inl_b, srcf, CSz, C_);
        const float* tf = srcf; srcf = dstf; dstf = (float*)tf;
        const __half* th = srch; srch = dsth; dsth = (__half*)th;
    }

    // 5) proj + residual: out[o,s] = x[o,s] + proj_w[o,:].h[s,:] + proj_b[o]
    //    (m=s, n=o, bias[n], E=x)
    mm16_kernel<2><<<dim3(4, 8, B_), 256, SMMM>>>(
        srch, C_, CSz,
        w16 + 1048576, C_, 0,
        out, nullptr, S_, CSz,
        proj_b, x, CSz, C_);
}

// round 16
// speedup vs baseline: 1.4777x; 1.0091x over previous
#include <cuda_runtime.h>
#include <cuda_fp16.h>
#include <cstdint>
#include <cstddef>

// ===========================================================================
// INLAttentionBlock, fp16 tensor-core pipeline (mma.sync m16n8k16, f32 accum):
// GN+T -> QKV -> flash(QK+softmax+PV) -> 3x INL -> proj+res
// B=8, C=512, S=1024, nh=8, hd=64. Activations token-major [b, s, c].
// MMA operands fp16; residual/Euler state kept in fp32 shadows.
// ===========================================================================

#define B_ 8
#define C_ 512
#define S_ 1024
#define NH 8
#define CS (C_ * S_)
#define CEXP 0.18033688011112042f   // 0.125 * log2(e)

__device__ __half g_hgn[(size_t)B_ * S_ * C_];        // [b, s, c] fp16
__device__ __half g_qkvT[(size_t)B_ * S_ * 1536];     // [b, s, 3C] fp16
__device__ float  g_h1f[(size_t)B_ * S_ * C_];        // fp32 shadow
__device__ __half g_h1h[(size_t)B_ * S_ * C_];
__device__ float  g_h2f[(size_t)B_ * S_ * C_];
__device__ __half g_h2h[(size_t)B_ * S_ * C_];
__device__ __half g_w16[1310720];                     // qkv|inl|proj fp16 weights
__device__ float2 g_part[512];

// ---------------------------------------------------------------------------
// helpers
// ---------------------------------------------------------------------------
__device__ __forceinline__ uint32_t smem_u32(const void* p) {
    uint32_t a;
    asm("{ .reg .u64 t; cvta.to.shared.u64 t, %1; cvt.u32.u64 %0, t; }" : "=r"(a) : "l"(p));
    return a;
}
__device__ __forceinline__ void ldsm4(uint32_t* r, uint32_t addr) {
    asm volatile("ldmatrix.sync.aligned.m8n8.x4.shared.b16 {%0,%1,%2,%3}, [%4];"
                 : "=r"(r[0]), "=r"(r[1]), "=r"(r[2]), "=r"(r[3]) : "r"(addr));
}
__device__ __forceinline__ void ldsm4t(uint32_t* r, uint32_t addr) {
    asm volatile("ldmatrix.sync.aligned.m8n8.x4.trans.shared.b16 {%0,%1,%2,%3}, [%4];"
                 : "=r"(r[0]), "=r"(r[1]), "=r"(r[2]), "=r"(r[3]) : "r"(addr));
}
__device__ __forceinline__ void mma16(float* d, const uint32_t* a, const uint32_t* b) {
    asm volatile("mma.sync.aligned.m16n8k16.row.col.f32.f16.f16.f32 "
                 "{%0,%1,%2,%3}, {%4,%5,%6,%7}, {%8,%9}, {%0,%1,%2,%3};"
                 : "+f"(d[0]), "+f"(d[1]), "+f"(d[2]), "+f"(d[3])
                 : "r"(a[0]), "r"(a[1]), "r"(a[2]), "r"(a[3]), "r"(b[0]), "r"(b[1]));
}
#define CP16(sa, ga) asm volatile("cp.async.cg.shared.global [%0], [%1], 16;" :: "r"(sa), "l"((const void*)(ga)))
#define CPCOMMIT()   asm volatile("cp.async.commit_group;" ::: "memory")
#define CPWAIT0()    asm volatile("cp.async.wait_group 0;" ::: "memory")

// ---------------------------------------------------------------------------
// weights fp32 -> fp16, single launch (blocks 0-383 qkv, 384-511 inl, 512-639 proj)
// ---------------------------------------------------------------------------
__global__ void f2h_all_kernel(const float* __restrict__ qkv_w,
                               const float* __restrict__ inl_w,
                               const float* __restrict__ proj_w,
                               __half* __restrict__ d) {
    int bb = blockIdx.x;
    const float* s;
    int base;
    if (bb < 384)      { s = qkv_w;  base = bb * 2048; }
    else if (bb < 512) { s = inl_w;  base = (bb - 384) * 2048; d += 786432; }
    else               { s = proj_w; base = (bb - 512) * 2048; d += 1048576; }
    int i = base + threadIdx.x * 8;
    float4 a = *(const float4*)(s + i);
    float4 b = *(const float4*)(s + i + 4);
    union { __half2 h[4]; uint4 u; } pk;
    pk.h[0] = __floats2half2_rn(a.x, a.y);
    pk.h[1] = __floats2half2_rn(a.z, a.w);
    pk.h[2] = __floats2half2_rn(b.x, b.y);
    pk.h[3] = __floats2half2_rn(b.z, b.w);
    *(uint4*)(d + i) = pk.u;
}

// ---------------------------------------------------------------------------
// GroupNorm partial stats (512 CTAs; 8 channels each)
// ---------------------------------------------------------------------------
__global__ void gn_stats_a_kernel(const float* __restrict__ x, float2* __restrict__ part) {
    __shared__ float sh[256], sh2[256];
    const int tid = threadIdx.x;
    const float4* p = (const float4*)(x + (size_t)blockIdx.x * 8192);
    float s = 0.f, s2 = 0.f;
#pragma unroll
    for (int r = 0; r < 8; r++) {
        float4 v = p[tid + r * 256];
        s  += v.x + v.y + v.z + v.w;
        s2 += v.x * v.x + v.y * v.y + v.z * v.z + v.w * v.w;
    }
    sh[tid] = s; sh2[tid] = s2;
    __syncthreads();
    for (int st = 128; st > 0; st >>= 1) {
        if (tid < st) { sh[tid] += sh[tid + st]; sh2[tid] += sh2[tid + st]; }
        __syncthreads();
    }
    if (tid == 0) part[blockIdx.x] = make_float2(sh[0], sh2[0]);
}

// ---------------------------------------------------------------------------
// GN apply + transpose, with fused final stats reduce + uint2 (half4) stores.
// Each CTA's 32-channel tile lies inside one 64-channel group, so thread 0
// reduces that group's 8 partials locally (no separate reduce kernel).
// ---------------------------------------------------------------------------
__global__ void gn_apply_t_kernel(const float* __restrict__ x, const float2* __restrict__ part,
                                  const float* __restrict__ sc, const float* __restrict__ bi,
                                  __half* __restrict__ hgn) {
    __shared__ float t[32][33];
    __shared__ float s_mean, s_rstd;
    const int b = blockIdx.z;
    const int c0 = blockIdx.y * 32;
    const int s0 = blockIdx.x * 32;
    const int tx = threadIdx.x, ty = threadIdx.y;
    const int tid = ty * 32 + tx;

    if (tid == 0) {
        const int g = c0 >> 6;
        float s = 0.f, s2 = 0.f;
#pragma unroll
        for (int i = 0; i < 8; i++) {
            float2 p = part[b * 64 + g * 8 + i];
            s += p.x; s2 += p.y;
        }
        float mean = s * (1.f / 65536.f);
        float var  = s2 * (1.f / 65536.f) - mean * mean;
        s_mean = mean;
        s_rstd = rsqrtf(var + 1e-5f);
    }
    __syncthreads();
    const float mean = s_mean, rstd = s_rstd;

#pragma unroll
    for (int r = 0; r < 4; r++) {
        int cl = ty + r * 8;
        int c = c0 + cl;
        float a = rstd * sc[c];
        float bb = bi[c] - mean * a;
        t[cl][tx] = x[(size_t)b * CS + (size_t)c * S_ + s0 + tx] * a + bb;
    }
    __syncthreads();

    // 256 threads cover 32 rows x 8 half4 slots -> STG.64, conflict-free reads
    {
        int row = tid >> 3;          // 0..31 (s within tile)
        int c4  = (tid & 7) * 4;     // 0,4,...,28 (channel within tile)
        int s = s0 + row;
        union { __half2 h[2]; uint2 u; } pk;
        pk.h[0] = __floats2half2_rn(t[c4 + 0][row], t[c4 + 1][row]);
        pk.h[1] = __floats2half2_rn(t[c4 + 2][row], t[c4 + 3][row]);
        *(uint2*)(hgn + (size_t)b * CS + (size_t)s * C_ + c0 + c4) = pk.u;
    }
}

// ---------------------------------------------------------------------------
// Flash attention fp16: CTA = (b,h, 128 q rows). 256 thr / 8 warps.
// SMEM: [0,32K) warp P slices (Q staged in [0,16K) first),
//       [32K,64K) K0|V0, [64K,96K) K1|V1. K,V tiles: [t(128) x 64h] 128B rows.
// ---------------------------------------------------------------------------
__global__ void __launch_bounds__(256, 1) flash_kernel(
    const __half* __restrict__ qkvT, float* __restrict__ of, __half* __restrict__ oh)
{
    extern __shared__ char sm[];
    const uint32_t sb = smem_u32(sm);
    const int tid = threadIdx.x, wid = tid >> 5, lane = tid & 31;
    const int grp = lane >> 2, tig = lane & 3;
    const int b = blockIdx.z >> 3, h = blockIdx.z & 7;
    const int q0 = blockIdx.x * 128;
    const int wm0 = wid * 16;

    const __half* Qg = qkvT + (size_t)b * S_ * 1536 + (size_t)q0 * 1536 + h * 64;
    const __half* Kg = qkvT + (size_t)b * S_ * 1536 + 512 + h * 64;

    uint32_t so[4]; int go[4];
#pragma unroll
    for (int r = 0; r < 4; r++) {
        int li = tid + r * 256;
        int row = li >> 3, c8 = li & 7;
        so[r] = (uint32_t)(row * 128 + c8 * 16) ^ ((uint32_t)(row & 7) << 4);
        go[r] = row * 1536 + c8 * 8;
    }

    const uint32_t KV0 = sb + 32768;
#pragma unroll
    for (int r = 0; r < 4; r++) CP16(sb + so[r], Qg + go[r]);
#pragma unroll
    for (int r = 0; r < 4; r++) CP16(KV0 + so[r], Kg + go[r]);
#pragma unroll
    for (int r = 0; r < 4; r++) CP16(KV0 + 16384 + so[r], Kg + 512 + go[r]);
    CPCOMMIT(); CPWAIT0();
    __syncthreads();

    const int rowA = lane & 15;
    const uint32_t kxA = (uint32_t)(lane >> 4) * 16;
    const uint32_t swzA = (uint32_t)(rowA & 7) << 4;
    const int rowB4 = (lane & 7) | (((lane >> 4) & 1) << 3);
    const uint32_t kxB4 = (uint32_t)((lane >> 3) & 1) * 16;
    const uint32_t swzB4 = (uint32_t)(rowB4 & 7) << 4;

    uint32_t qf[4][4];
#pragma unroll
    for (int ks = 0; ks < 4; ks++)
        ldsm4(qf[ks], sb + (uint32_t)((wm0 + rowA) * 128) + (((uint32_t)(ks * 32) + kxA) ^ swzA));
    __syncthreads();

    float m0 = -1e30f, m1 = -1e30f, l0 = 0.f, l1 = 0.f;
    float oacc[8][4];
#pragma unroll
    for (int nt = 0; nt < 8; nt++)
#pragma unroll
        for (int r = 0; r < 4; r++) oacc[nt][r] = 0.f;

    const uint32_t Pw = sb + (uint32_t)wid * 4096;

    for (int kv = 0; kv < 8; kv++) {
        const uint32_t Kb = sb + 32768 + (uint32_t)(kv & 1) * 32768;
        const uint32_t Vb = Kb + 16384;

        if (kv + 1 < 8) {
            const uint32_t Kn = sb + 32768 + (uint32_t)((kv + 1) & 1) * 32768;
            const __half* Kg2 = Kg + (size_t)(kv + 1) * 128 * 1536;
#pragma unroll
            for (int r = 0; r < 4; r++) CP16(Kn + so[r], Kg2 + go[r]);
#pragma unroll
            for (int r = 0; r < 4; r++) CP16(Kn + 16384 + so[r], Kg2 + 512 + go[r]);
            CPCOMMIT();
        }

        // ---- S = Q K^T ----
        float sacc[16][4];
#pragma unroll
        for (int nt = 0; nt < 16; nt++)
#pragma unroll
            for (int r = 0; r < 4; r++) sacc[nt][r] = 0.f;
#pragma unroll
        for (int ks = 0; ks < 4; ks++) {
#pragma unroll
            for (int np = 0; np < 8; np++) {
                uint32_t bf[4];
                ldsm4(bf, Kb + (uint32_t)((np * 16 + rowB4) * 128)
                          + (((uint32_t)(ks * 32) + kxB4) ^ swzB4));
                mma16(sacc[np * 2], qf[ks], bf);
                mma16(sacc[np * 2 + 1], qf[ks], bf + 2);
            }
        }

        // ---- online softmax ----
        float r0 = -1e30f, r1 = -1e30f;
#pragma unroll
        for (int nt = 0; nt < 16; nt++) {
            r0 = fmaxf(r0, fmaxf(sacc[nt][0], sacc[nt][1]));
            r1 = fmaxf(r1, fmaxf(sacc[nt][2], sacc[nt][3]));
        }
        r0 = fmaxf(r0, __shfl_xor_sync(0xffffffffu, r0, 1));
        r0 = fmaxf(r0, __shfl_xor_sync(0xffffffffu, r0, 2));
        r1 = fmaxf(r1, __shfl_xor_sync(0xffffffffu, r1, 1));
        r1 = fmaxf(r1, __shfl_xor_sync(0xffffffffu, r1, 2));
        float mn0 = fmaxf(m0, r0), mn1 = fmaxf(m1, r1);
        float a0 = exp2f((m0 - mn0) * CEXP);
        float a1 = exp2f((m1 - mn1) * CEXP);
        m0 = mn0; m1 = mn1;
        l0 *= a0; l1 *= a1;
#pragma unroll
        for (int nt = 0; nt < 8; nt++) {
            oacc[nt][0] *= a0; oacc[nt][1] *= a0;
            oacc[nt][2] *= a1; oacc[nt][3] *= a1;
        }
#pragma unroll
        for (int nt = 0; nt < 16; nt++) {
            float p0 = exp2f((sacc[nt][0] - m0) * CEXP);
            float p1 = exp2f((sacc[nt][1] - m0) * CEXP);
            float p2 = exp2f((sacc[nt][2] - m1) * CEXP);
            float p3 = exp2f((sacc[nt][3] - m1) * CEXP);
            l0 += p0 + p1; l1 += p2 + p3;
            int t = nt * 8 + tig * 2;
            uint32_t off = (Pw - sb) + (uint32_t)(t >> 6) * 2048 + (uint32_t)(grp * 128)
                           + (((uint32_t)(t & 63) * 2) ^ ((uint32_t)grp << 4));
            *(__half2*)(sm + off)        = __floats2half2_rn(p0, p1);
            *(__half2*)(sm + off + 1024) = __floats2half2_rn(p2, p3);
        }
        __syncwarp();

        // ---- O += P V ----
#pragma unroll
        for (int kt = 0; kt < 8; kt++) {
            uint32_t pf[4];
            ldsm4(pf, Pw + (uint32_t)(kt >> 2) * 2048 + (uint32_t)(rowA * 128)
                      + (((uint32_t)((kt & 3) * 32) + kxA) ^ swzA));
#pragma unroll
            for (int np = 0; np < 4; np++) {
                uint32_t bf[4];
                ldsm4t(bf, Vb + (uint32_t)((kt * 16 + rowA) * 128)
                           + (((uint32_t)(np * 32) + ((uint32_t)(lane >> 4) * 16)) ^ swzA));
                mma16(oacc[np * 2], pf, bf);
                mma16(oacc[np * 2 + 1], pf, bf + 2);
            }
        }

        if (kv + 1 < 8) CPWAIT0();
        __syncthreads();
    }

    // ---- finalize ----
    l0 += __shfl_xor_sync(0xffffffffu, l0, 1);
    l0 += __shfl_xor_sync(0xffffffffu, l0, 2);
    l1 += __shfl_xor_sync(0xffffffffu, l1, 1);
    l1 += __shfl_xor_sync(0xffffffffu, l1, 2);
    float i0 = 1.f / l0, i1 = 1.f / l1;
    const int sg = q0 + wm0 + grp;
    size_t ob = (size_t)b * CS + (size_t)sg * 512 + h * 64 + tig * 2;
#pragma unroll
    for (int nt = 0; nt < 8; nt++) {
        float x0 = oacc[nt][0] * i0, x1 = oacc[nt][1] * i0;
        float x2 = oacc[nt][2] * i1, x3 = oacc[nt][3] * i1;
        *(float2*)(of + ob + nt * 8)            = make_float2(x0, x1);
        *(float2*)(of + ob + 8 * 512 + nt * 8)  = make_float2(x2, x3);
        *(__half2*)(oh + ob + nt * 8)           = __floats2half2_rn(x0, x1);
        *(__half2*)(oh + ob + 8 * 512 + nt * 8) = __floats2half2_rn(x2, x3);
    }
}

// ---------------------------------------------------------------------------
// fp16 GEMM: D[m,n] = epi( sum_k A[m,k]*B[n,k] ), A/B fp16 K-contig.
// BM=128, BN=128, BK=64. EPI: 0 QKV(out fp16, +bias[m]);
// 1 INL(out f32+f16, E + 0.1*tanh(v+bias[m])); 2 proj(out f32, E + v + bias[n]).
// ---------------------------------------------------------------------------
template <int EPI>
__global__ void __launch_bounds__(256) mm16_kernel(
    const __half* __restrict__ Abase, int ldA, size_t sAo,
    const __half* __restrict__ Bbase, int ldB, size_t sBo,
    float* __restrict__ O32, __half* __restrict__ O16, int ldO, size_t sOo,
    const float* __restrict__ bias,
    const float* __restrict__ Ebase, size_t sEo,
    int K)
{
    constexpr int ABYTES = 16384;       // 128 x 64 halves
    constexpr int STAGE  = 32768;
    constexpr int PITCH  = 132;

    extern __shared__ char smemc[];
    const uint32_t sb = smem_u32(smemc);
    const int tid = threadIdx.x;
    const int wid = tid >> 5;
    const int lane = tid & 31;
    const int grp = lane >> 2, tig = lane & 3;

    const int z = blockIdx.z;
    const __half* Ag = Abase + (size_t)z * sAo;
    const __half* Bg = Bbase + (size_t)z * sBo;
    const float*  E  = (EPI != 0) ? (Ebase + (size_t)z * sEo) : nullptr;

    const int m0 = blockIdx.y * 128;
    const int n0 = blockIdx.x * 128;
    const int wm0 = (wid & 1) * 64;
    const int wn0 = (wid >> 1) * 32;

    uint32_t asw[4];
    size_t ago[4], bgo[4];
#pragma unroll
    for (int r = 0; r < 4; r++) {
        int li = tid + r * 256;
        int row = li >> 3, c8 = li & 7;
        asw[r] = (uint32_t)(row * 128 + c8 * 16) ^ ((uint32_t)(row & 7) << 4);
        ago[r] = (size_t)(m0 + row) * ldA + c8 * 8;
        bgo[r] = (size_t)(n0 + row) * ldB + c8 * 8;
    }

    const int rowA = lane & 15;
    const uint32_t kxA = (uint32_t)(lane >> 4) * 16;
    const uint32_t swzA = (uint32_t)(rowA & 7) << 4;
    const int rowB4 = (lane & 7) | (((lane >> 4) & 1) << 3);
    const uint32_t kxB4 = (uint32_t)((lane >> 3) & 1) * 16;
    const uint32_t swzB4 = (uint32_t)(rowB4 & 7) << 4;

    float acc[4][4][4];
#pragma unroll
    for (int mt = 0; mt < 4; mt++)
#pragma unroll
        for (int nt = 0; nt < 4; nt++)
#pragma unroll
            for (int r = 0; r < 4; r++) acc[mt][nt][r] = 0.f;

    const int nkt = K >> 6;

    // prologue: tile 0
#pragma unroll
    for (int r = 0; r < 4; r++) { CP16(sb + asw[r], Ag + ago[r]); CP16(sb + ABYTES + asw[r], Bg + bgo[r]); }
    CPCOMMIT(); CPWAIT0();
    __syncthreads();

    for (int kt = 0; kt < nkt; kt++) {
        const int cur = kt & 1;
        const uint32_t As = sb + cur * STAGE;
        const uint32_t Bs = As + ABYTES;

        if (kt + 1 < nkt) {
            const uint32_t nb = sb + (cur ^ 1) * STAGE;
            const int k0 = (kt + 1) << 6;
#pragma unroll
            for (int r = 0; r < 4; r++) { CP16(nb + asw[r], Ag + ago[r] + k0); CP16(nb + ABYTES + asw[r], Bg + bgo[r] + k0); }
            CPCOMMIT();
        }

#pragma unroll
        for (int ks = 0; ks < 4; ks++) {
            uint32_t afr[4][4];
#pragma unroll
            for (int mt = 0; mt < 4; mt++)
                ldsm4(afr[mt], As + (uint32_t)((wm0 + mt * 16 + rowA) * 128)
                              + (((uint32_t)(ks * 32) + kxA) ^ swzA));
            uint32_t bfr[2][4];
#pragma unroll
            for (int np = 0; np < 2; np++)
                ldsm4(bfr[np], Bs + (uint32_t)((wn0 + np * 16 + rowB4) * 128)
                              + (((uint32_t)(ks * 32) + kxB4) ^ swzB4));
#pragma unroll
            for (int mt = 0; mt < 4; mt++)
#pragma unroll
                for (int np = 0; np < 2; np++) {
                    mma16(acc[mt][np * 2], afr[mt], bfr[np]);
                    mma16(acc[mt][np * 2 + 1], afr[mt], bfr[np] + 2);
                }
        }

        if (kt + 1 < nkt) { CPWAIT0(); __syncthreads(); }
    }

    // ---- epilogue: transpose through SMEM ([n][m] fp32) ----
    __syncthreads();
    float* Csm = (float*)smemc;
#pragma unroll
    for (int mt = 0; mt < 4; mt++) {
#pragma unroll
        for (int nt = 0; nt < 4; nt++) {
            int m = wm0 + mt * 16 + grp;
            int n = wn0 + nt * 8 + tig * 2;
            Csm[(n)     * PITCH + m]     = acc[mt][nt][0];
            Csm[(n + 1) * PITCH + m]     = acc[mt][nt][1];
            Csm[(n)     * PITCH + m + 8] = acc[mt][nt][2];
            Csm[(n + 1) * PITCH + m + 8] = acc[mt][nt][3];
        }
    }
    __syncthreads();

#pragma unroll
    for (int it = 0; it < 16; it++) {
        int li = tid + it * 256;
        int n = li >> 5, m4 = (li & 31) << 2;
        float4 c = *(float4*)(Csm + n * PITCH + m4);
        size_t idx = (size_t)z * sOo + (size_t)(n0 + n) * ldO + m0 + m4;
        if (EPI == 0) {
            float4 bm = *(const float4*)(bias + m0 + m4);
            union { __half2 h[2]; uint2 u; } pk;
            pk.h[0] = __floats2half2_rn(c.x + bm.x, c.y + bm.y);
            pk.h[1] = __floats2half2_rn(c.z + bm.z, c.w + bm.w);
            *(uint2*)(O16 + idx) = pk.u;
        } else if (EPI == 1) {
            float4 bm = *(const float4*)(bias + m0 + m4);
            float4 e = *(const float4*)(E + (size_t)(n0 + n) * ldO + m0 + m4);
            float4 r;
            r.x = e.x + 0.1f * tanhf(c.x + bm.x);
            r.y = e.y + 0.1f * tanhf(c.y + bm.y);
            r.z = e.z + 0.1f * tanhf(c.z + bm.z);
            r.w = e.w + 0.1f * tanhf(c.w + bm.w);
            *(float4*)(O32 + idx) = r;
            union { __half2 h[2]; uint2 u; } pk;
            pk.h[0] = __floats2half2_rn(r.x, r.y);
            pk.h[1] = __floats2half2_rn(r.z, r.w);
            *(uint2*)(O16 + idx) = pk.u;
        } else {
            float bn = bias[n0 + n];
            float4 e = *(const float4*)(E + (size_t)(n0 + n) * ldO + m0 + m4);
            c.x += e.x + bn; c.y += e.y + bn; c.z += e.z + bn; c.w += e.w + bn;
            *(float4*)(O32 + idx) = c;
        }
    }
}

// ---------------------------------------------------------------------------
// Host launcher
// ---------------------------------------------------------------------------
extern "C" void kernel_launch(void* const* d_in, const int* in_sizes, int n_in,
                              void* d_out, int out_size) {
    const float* x        = (const float*)d_in[0];
    const float* gn_scale = (const float*)d_in[1];
    const float* gn_bias  = (const float*)d_in[2];
    const float* qkv_w    = (const float*)d_in[3];
    const float* qkv_b    = (const float*)d_in[4];
    const float* proj_w   = (const float*)d_in[5];
    const float* proj_b   = (const float*)d_in[6];
    const float* inl_w    = (const float*)d_in[7];
    const float* inl_b    = (const float*)d_in[8];
    float* out = (float*)d_out;

    __half *hgn, *qkvT, *h1h, *h2h, *w16;
    float *h1f, *h2f;
    float2* part;
    cudaGetSymbolAddress((void**)&hgn,   g_hgn);
    cudaGetSymbolAddress((void**)&qkvT,  g_qkvT);
    cudaGetSymbolAddress((void**)&h1f,   g_h1f);
    cudaGetSymbolAddress((void**)&h1h,   g_h1h);
    cudaGetSymbolAddress((void**)&h2f,   g_h2f);
    cudaGetSymbolAddress((void**)&h2h,   g_h2h);
    cudaGetSymbolAddress((void**)&w16,   g_w16);
    cudaGetSymbolAddress((void**)&part,  g_part);

    const int SMMM = 132 * 128 * 4;   // 67584 (>= 2*32768)
    const int SMFL = 98304;
    cudaFuncSetAttribute(mm16_kernel<0>, cudaFuncAttributeMaxDynamicSharedMemorySize, SMMM);
    cudaFuncSetAttribute(mm16_kernel<1>, cudaFuncAttributeMaxDynamicSharedMemorySize, SMMM);
    cudaFuncSetAttribute(mm16_kernel<2>, cudaFuncAttributeMaxDynamicSharedMemorySize, SMMM);
    cudaFuncSetAttribute(flash_kernel,   cudaFuncAttributeMaxDynamicSharedMemorySize, SMFL);

    const size_t CSz = (size_t)CS;

    // 0) weights -> fp16 (single launch)
    f2h_all_kernel<<<640, 256>>>(qkv_w, inl_w, proj_w, w16);

    // 1) GroupNorm: partial stats, then fused reduce+apply+transpose
    gn_stats_a_kernel<<<512, 256>>>(x, part);
    gn_apply_t_kernel<<<dim3(32, 16, B_), dim3(32, 8)>>>(x, part, gn_scale, gn_bias, hgn);

    // 2) QKV: qkvT[s,o] fp16 = qkv_w[o,:].hgn[s,:] + qkv_b[o]   (m=o, n=s)
    mm16_kernel<0><<<dim3(8, 12, B_), 256, SMMM>>>(
        w16, C_, 0,
        hgn, C_, CSz,
        nullptr, qkvT, 1536, (size_t)S_ * 1536,
        qkv_b, nullptr, 0, C_);

    // 3) fused attention -> h1 (f32 + f16)
    flash_kernel<<<dim3(8, 1, B_ * NH), 256, SMFL>>>(qkvT, h1f, h1h);

    // 4) INL x3
    const float* srcf = h1f; const __half* srch = h1h;
    float* dstf = h2f; __half* dsth = h2h;
    for (int it = 0; it < 3; it++) {
        mm16_kernel<1><<<dim3(8, 4, B_), 256, SMMM>>>(
            w16 + 786432, C_, 0,
            srch, C_, CSz,
            dstf, dsth, C_, CSz,
            inl_b, srcf, CSz, C_);
        const float* tf = srcf; srcf = dstf; dstf = (float*)tf;
        const __half* th = srch; srch = dsth; dsth = (__half*)th;
    }

    // 5) proj + residual: out[o,s] = x[o,s] + proj_w[o,:].h[s,:] + proj_b[o]
    //    (m=s, n=o, bias[n], E=x)
    mm16_kernel<2><<<dim3(4, 8, B_), 256, SMMM>>>(
        srch, C_, CSz,
        w16 + 1048576, C_, 0,
        out, nullptr, S_, CSz,
        proj_b, x, CSz, C_);
}